// round 10
// baseline (speedup 1.0000x reference)
#include <cuda_runtime.h>
#include <cuda_fp16.h>
#include <cstdint>

#define HF 128
#define HV 32           // float4 per feature row
#define NMAX 50048
#define EMAX 800032

// ---------------- scratch (static device memory; no allocation) ----------------
__device__ float g_hn[NMAX * HF];        // relu(BN(x))
__device__ float g_u [NMAX * HF];        // agg + hn  (MLP input)
__device__ float g_y1[NMAX * 2 * HF];    // GEMM1 output (pre-LN), L2-resident
__device__ int   g_cnt[NMAX];
__device__ int   g_rs [NMAX + 1];
__device__ int   g_cur[NMAX];
__device__ int2  g_edges[EMAX];
// fragment-ordered fp16 weight images (hi / lo*512 splits), 64KB each
__device__ uint2 g_w1h[8192], g_w1l[8192];
__device__ uint2 g_w2h[8192], g_w2l[8192];

#define LO_SCALE 512.0f
#define LO_INV   (1.0f / 512.0f)

// ---------------- helpers ----------------
// fp16 hi/lo split of a float pair; lo digit pre-scaled by LO_SCALE (keeps it normal-range)
__device__ __forceinline__ void hsplit2(float a, float b, uint32_t& hi, uint32_t& lo) {
    __half2 h = __floats2half2_rn(a, b);
    float2 hf = __half22float2(h);
    __half2 l = __floats2half2_rn((a - hf.x) * LO_SCALE, (b - hf.y) * LO_SCALE);
    hi = *reinterpret_cast<uint32_t*>(&h);
    lo = *reinterpret_cast<uint32_t*>(&l);
}

__device__ __forceinline__ float2 h2_to_f2(uint32_t v) {
    __half2 h = *reinterpret_cast<__half2*>(&v);
    return __half22float2(h);
}

// main term: f16 inputs, f32 accum
__device__ __forceinline__ void mma_f32acc(float* d, const uint32_t* a, uint32_t b0, uint32_t b1) {
    asm volatile(
        "mma.sync.aligned.m16n8k16.row.col.f32.f16.f16.f32 "
        "{%0,%1,%2,%3}, {%4,%5,%6,%7}, {%8,%9}, {%0,%1,%2,%3};"
        : "+f"(d[0]), "+f"(d[1]), "+f"(d[2]), "+f"(d[3])
        : "r"(a[0]), "r"(a[1]), "r"(a[2]), "r"(a[3]), "r"(b0), "r"(b1));
}

// correction terms: f16 inputs, f16 accum (2 half2 regs)
__device__ __forceinline__ void mma_f16acc(uint32_t* d, const uint32_t* a, uint32_t b0, uint32_t b1) {
    asm volatile(
        "mma.sync.aligned.m16n8k16.row.col.f16.f16.f16.f16 "
        "{%0,%1}, {%2,%3,%4,%5}, {%6,%7}, {%0,%1};"
        : "+r"(d[0]), "+r"(d[1])
        : "r"(a[0]), "r"(a[1]), "r"(a[2]), "r"(a[3]), "r"(b0), "r"(b1));
}

// ---------------- K0: hn = relu(BN(h))  +  degree histogram ----------------
__global__ void k_hn_hist(const float4* __restrict__ h,
                          const float4* __restrict__ bw, const float4* __restrict__ bb,
                          const float4* __restrict__ bm, const float4* __restrict__ bv,
                          const int* __restrict__ dst, int n, int e)
{
    int i = blockIdx.x * blockDim.x + threadIdx.x;
    if (i < e) atomicAdd(&g_cnt[dst[i]], 1);
    if (i >= n * HV) return;
    int j = i & (HV - 1);
    float4 x = h[i];
    float4 w = bw[j], b = bb[j], m = bm[j], v = bv[j];
    float4 o;
    o.x = fmaxf((x.x - m.x) * rsqrtf(v.x + 1e-5f) * w.x + b.x, 0.f);
    o.y = fmaxf((x.y - m.y) * rsqrtf(v.y + 1e-5f) * w.y + b.y, 0.f);
    o.z = fmaxf((x.z - m.z) * rsqrtf(v.z + 1e-5f) * w.z + b.z, 0.f);
    o.w = fmaxf((x.w - m.w) * rsqrtf(v.w + 1e-5f) * w.w + b.w, 0.f);
    ((float4*)g_hn)[i] = o;
}

// ---------------- K1: coalesced exclusive scan (single block) ----------------
__global__ void k_scan(int n)
{
    __shared__ int wsum[32];
    __shared__ int s_carry;
    int tid = threadIdx.x, lane = tid & 31, wid = tid >> 5;
    if (tid == 0) s_carry = 0;
    __syncthreads();
    int nIter = (n + 1023) >> 10;
    for (int it = 0; it < nIter; ++it) {
        int idx = (it << 10) + tid;
        int v = (idx < n) ? g_cnt[idx] : 0;
        int x = v;
        #pragma unroll
        for (int o = 1; o < 32; o <<= 1) {
            int u = __shfl_up_sync(0xffffffffu, x, o);
            if (lane >= o) x += u;
        }
        if (lane == 31) wsum[wid] = x;
        __syncthreads();
        if (wid == 0) {
            int w = wsum[lane];
            #pragma unroll
            for (int o = 1; o < 32; o <<= 1) {
                int u = __shfl_up_sync(0xffffffffu, w, o);
                if (lane >= o) w += u;
            }
            wsum[lane] = w;
        }
        __syncthreads();
        int carry = s_carry;
        int excl = x - v + (wid > 0 ? wsum[wid - 1] : 0) + carry;
        if (idx < n) { g_rs[idx] = excl; g_cur[idx] = excl; g_cnt[idx] = 0; }
        __syncthreads();
        if (tid == 0) s_carry = carry + wsum[31];
        __syncthreads();
    }
    if (tid == 0) g_rs[n] = s_carry;
}

// ---------------- K2: scatter edges by dst ----------------
__global__ void k_scatter(const int* __restrict__ src, const int* __restrict__ dst, int e)
{
    int i = blockIdx.x * blockDim.x + threadIdx.x;
    if (i >= e) return;
    int d = dst[i];
    int s = src[i];
    int p = atomicAdd(&g_cur[d], 1);
    g_edges[p] = make_int2(s, i);
}

// ---------------- K3: one-pass softmax aggregation (warp per dst node) ----------------
#define EDGE_ACC(a, hv)                                               \
    {                                                                 \
        float m0 = fmaxf(a.x + hv.x, 0.f) + 1e-7f;                    \
        float m1 = fmaxf(a.y + hv.y, 0.f) + 1e-7f;                    \
        float m2 = fmaxf(a.z + hv.z, 0.f) + 1e-7f;                    \
        float m3 = fmaxf(a.w + hv.w, 0.f) + 1e-7f;                    \
        float e0 = __expf(m0 * t);                                    \
        float e1 = __expf(m1 * t);                                    \
        float e2 = __expf(m2 * t);                                    \
        float e3 = __expf(m3 * t);                                    \
        S.x += e0; P.x = fmaf(m0, e0, P.x);                           \
        S.y += e1; P.y = fmaf(m1, e1, P.y);                           \
        S.z += e2; P.z = fmaf(m2, e2, P.z);                           \
        S.w += e3; P.w = fmaf(m3, e3, P.w);                           \
    }

__global__ void __launch_bounds__(256) k_agg(const float4* __restrict__ ea,
                                             const float* __restrict__ tp, int n)
{
    int warp = (blockIdx.x * blockDim.x + threadIdx.x) >> 5;
    int lane = threadIdx.x & 31;
    if (warp >= n) return;
    float t = __ldg(tp);
    int s0 = g_rs[warp], s1 = g_rs[warp + 1];
    const float4* hn4 = (const float4*)g_hn;
    float4 S = make_float4(0.f, 0.f, 0.f, 0.f);
    float4 P = make_float4(0.f, 0.f, 0.f, 0.f);

    int i = s0;
    for (; i + 4 <= s1; i += 4) {
        int2 q0 = g_edges[i + 0];
        int2 q1 = g_edges[i + 1];
        int2 q2 = g_edges[i + 2];
        int2 q3 = g_edges[i + 3];
        float4 a0 = ea [(size_t)q0.y * HV + lane];
        float4 h0 = hn4[(size_t)q0.x * HV + lane];
        float4 a1 = ea [(size_t)q1.y * HV + lane];
        float4 h1 = hn4[(size_t)q1.x * HV + lane];
        float4 a2 = ea [(size_t)q2.y * HV + lane];
        float4 h2 = hn4[(size_t)q2.x * HV + lane];
        float4 a3 = ea [(size_t)q3.y * HV + lane];
        float4 h3 = hn4[(size_t)q3.x * HV + lane];
        EDGE_ACC(a0, h0);
        EDGE_ACC(a1, h1);
        EDGE_ACC(a2, h2);
        EDGE_ACC(a3, h3);
    }
    for (; i < s1; ++i) {
        int2 q = g_edges[i];
        float4 a  = ea [(size_t)q.y * HV + lane];
        float4 hv = hn4[(size_t)q.x * HV + lane];
        EDGE_ACC(a, hv);
    }

    float4 hd = hn4[warp * HV + lane];
    float4 u;
    u.x = P.x / (S.x + 1e-16f) + hd.x;
    u.y = P.y / (S.y + 1e-16f) + hd.y;
    u.z = P.z / (S.z + 1e-16f) + hd.z;
    u.w = P.w / (S.w + 1e-16f) + hd.w;
    ((float4*)g_u)[warp * HV + lane] = u;
}

// ---------------- K4: prep fragment-ordered fp16 weight images ----------------
// W1: idx = ks(8)*1024 + nb(32)*32 + lane.  W2: idx = ks(16)*512 + nb(16)*32 + lane.
// B frag (16x8 col-major): b0 = rows {k0, k0+1}, b1 = rows {k0+8, k0+9}, col n.
__global__ void k_prepw(const float* __restrict__ W1, const float* __restrict__ W2)
{
    int idx = blockIdx.x * blockDim.x + threadIdx.x;
    if (idx >= 16384) return;
    const float* W;
    uint2 *ih, *il;
    int ks, nb, l, ldn;
    if (idx < 8192) {
        int j = idx;
        ks = j >> 10; nb = (j >> 5) & 31; l = j & 31;
        W = W1; ih = g_w1h; il = g_w1l; ldn = 256;
    } else {
        int j = idx - 8192;
        ks = j >> 9; nb = (j >> 5) & 15; l = j & 31;
        W = W2; ih = g_w2h; il = g_w2l; ldn = 128;
    }
    int k0 = ks * 16 + (l & 3) * 2;
    int nn = nb * 8 + (l >> 2);
    float x00 = W[(size_t)(k0 + 0) * ldn + nn];
    float x01 = W[(size_t)(k0 + 1) * ldn + nn];
    float x10 = W[(size_t)(k0 + 8) * ldn + nn];
    float x11 = W[(size_t)(k0 + 9) * ldn + nn];
    uint32_t b0h, b0l, b1h, b1l;
    hsplit2(x00, x01, b0h, b0l);
    hsplit2(x10, x11, b1h, b1l);
    ih[idx & 8191] = make_uint2(b0h, b1h);
    il[idx & 8191] = make_uint2(b0l, b1l);
}

// ---------------- K5: GEMM1 via mma.sync  y1 = u @ W1 + b1 ----------------
// 304 CTAs = 2/SM; CTA owns a 128-col half; 2 passes of 8 nb (regs); corrections in f16-accum.
#define SMEM_MMA1 (65536 + 512)
__global__ void __launch_bounds__(256, 2) k_mma1(const float* __restrict__ b1,
                                                 int n, int nstrips)
{
    extern __shared__ char smem[];
    uint2* sWh  = (uint2*)smem;             // 4096 (32KB): 8 ks x 16 nb x 32 lanes
    uint2* sWl  = (uint2*)(smem + 32768);   // 4096 (32KB)
    float* s_b1 = (float*)(smem + 65536);   // 128
    int tid = threadIdx.x, wid = tid >> 5, lane = tid & 31;
    int half = blockIdx.x & 1, slot = blockIdx.x >> 1;

    for (int i = tid; i < 4096; i += 256) {
        int ks = i >> 9, rem = i & 511;
        int gidx = ks * 1024 + half * 512 + rem;
        sWh[i] = g_w1h[gidx];
        sWl[i] = g_w1l[gidx];
    }
    if (tid < 128) s_b1[tid] = b1[half * 128 + tid];
    __syncthreads();

    int g = lane >> 2, t = lane & 3;
    int nwarps = 152 * 8;
    for (int strip = slot * 8 + wid; strip < nstrips; strip += nwarps) {
        int rg0 = strip * 16 + g;
        int rg1 = rg0 + 8;
        const float* up0 = g_u + (size_t)rg0 * 128;
        const float* up1 = g_u + (size_t)rg1 * 128;
        #pragma unroll
        for (int nq = 0; nq < 2; ++nq) {       // 128 cols of this half in 2 passes of 8 nb
            float    accF[8][4];
            uint32_t accH[8][2];
            #pragma unroll
            for (int nb = 0; nb < 8; ++nb) {
                accF[nb][0] = 0.f; accF[nb][1] = 0.f; accF[nb][2] = 0.f; accF[nb][3] = 0.f;
                accH[nb][0] = 0u;  accH[nb][1] = 0u;
            }
            #pragma unroll
            for (int ks = 0; ks < 8; ++ks) {
                int k0 = ks * 16 + t * 2;
                float2 v00 = *(const float2*)(up0 + k0);
                float2 v01 = *(const float2*)(up0 + k0 + 8);
                float2 v10 = *(const float2*)(up1 + k0);
                float2 v11 = *(const float2*)(up1 + k0 + 8);
                uint32_t ah[4], al[4];
                hsplit2(v00.x, v00.y, ah[0], al[0]);
                hsplit2(v10.x, v10.y, ah[1], al[1]);
                hsplit2(v01.x, v01.y, ah[2], al[2]);
                hsplit2(v11.x, v11.y, ah[3], al[3]);
                const uint2* wh = sWh + ks * 512 + nq * 256 + lane;
                const uint2* wl = sWl + ks * 512 + nq * 256 + lane;
                #pragma unroll
                for (int nb = 0; nb < 8; ++nb) {
                    uint2 bh = wh[nb * 32];
                    uint2 bl = wl[nb * 32];
                    mma_f32acc(accF[nb], ah, bh.x, bh.y);
                    mma_f16acc(accH[nb], ah, bl.x, bl.y);
                    mma_f16acc(accH[nb], al, bh.x, bh.y);
                }
            }
            #pragma unroll
            for (int nb = 0; nb < 8; ++nb) {
                int lcol = nq * 64 + nb * 8 + t * 2;
                int col = half * 128 + lcol;
                float2 bb = *(const float2*)(s_b1 + lcol);
                float2 c0 = h2_to_f2(accH[nb][0]);
                float2 c1 = h2_to_f2(accH[nb][1]);
                if (rg0 < n)
                    *(float2*)(g_y1 + (size_t)rg0 * 256 + col) =
                        make_float2(accF[nb][0] + c0.x * LO_INV + bb.x,
                                    accF[nb][1] + c0.y * LO_INV + bb.y);
                if (rg1 < n)
                    *(float2*)(g_y1 + (size_t)rg1 * 256 + col) =
                        make_float2(accF[nb][2] + c1.x * LO_INV + bb.x,
                                    accF[nb][3] + c1.y * LO_INV + bb.y);
            }
        }
    }
}

// ---------------- K6: GEMM2 via mma.sync  out = relu(LN(y1)) @ W2 + b2 + h ----------------
// 304 CTAs = 2/SM; CTA owns a 64-col half (8 nb); corrections in f16-accum.
#define SMEM_MMA2 (65536 + 2304)
__global__ void __launch_bounds__(256, 2) k_mma2(const float* __restrict__ b2,
                                                 const float* __restrict__ lnw,
                                                 const float* __restrict__ lnb,
                                                 const float* __restrict__ hres,
                                                 float* __restrict__ out,
                                                 int n, int nstrips)
{
    extern __shared__ char smem[];
    uint2* sWh   = (uint2*)smem;                     // 4096 (32KB)
    uint2* sWl   = (uint2*)(smem + 32768);           // 4096 (32KB)
    float* s_lnw = (float*)(smem + 65536);           // 256
    float* s_lnb = (float*)(smem + 65536 + 1024);    // 256
    float* s_b2  = (float*)(smem + 65536 + 2048);    // 64
    int tid = threadIdx.x, wid = tid >> 5, lane = tid & 31;
    int half = blockIdx.x & 1, slot = blockIdx.x >> 1;

    for (int i = tid; i < 4096; i += 256) {
        int ks = i >> 8, rem = i & 255;
        int gidx = ks * 512 + half * 256 + rem;
        sWh[i] = g_w2h[gidx];
        sWl[i] = g_w2l[gidx];
    }
    if (tid < 256) { s_lnw[tid] = lnw[tid]; s_lnb[tid] = lnb[tid]; }
    if (tid < 64) s_b2[tid] = b2[half * 64 + tid];
    __syncthreads();

    int g = lane >> 2, t = lane & 3;
    int nwarps = 152 * 8;
    for (int strip = slot * 8 + wid; strip < nstrips; strip += nwarps) {
        // ---- LN stats for the 16 rows of this strip ----
        float meanA = 0.f, scaleA = 0.f, meanB = 0.f, scaleB = 0.f;
        #pragma unroll
        for (int r = 0; r < 16; ++r) {
            int grow = strip * 16 + r;
            const float4* yp = (const float4*)(g_y1 + (size_t)grow * 256);
            float4 a = yp[lane * 2], b = yp[lane * 2 + 1];
            float s  = a.x + a.y + a.z + a.w + b.x + b.y + b.z + b.w;
            float s2 = a.x*a.x + a.y*a.y + a.z*a.z + a.w*a.w
                     + b.x*b.x + b.y*b.y + b.z*b.z + b.w*b.w;
            #pragma unroll
            for (int o = 16; o > 0; o >>= 1) {
                s  += __shfl_xor_sync(0xffffffffu, s, o);
                s2 += __shfl_xor_sync(0xffffffffu, s2, o);
            }
            float mean = s * (1.f / 256.f);
            float var = fmaxf(s2 * (1.f / 256.f) - mean * mean, 0.f);
            float sc = rsqrtf(var + 1e-5f);
            if (r == g)     { meanA = mean; scaleA = sc; }
            if (r == g + 8) { meanB = mean; scaleB = sc; }
        }

        int rg0 = strip * 16 + g, rg1 = rg0 + 8;
        const float* yp0 = g_y1 + (size_t)rg0 * 256;
        const float* yp1 = g_y1 + (size_t)rg1 * 256;
        float    accF[8][4];
        uint32_t accH[8][2];
        #pragma unroll
        for (int nb = 0; nb < 8; ++nb) {
            accF[nb][0] = 0.f; accF[nb][1] = 0.f; accF[nb][2] = 0.f; accF[nb][3] = 0.f;
            accH[nb][0] = 0u;  accH[nb][1] = 0u;
        }
        #pragma unroll
        for (int ks = 0; ks < 16; ++ks) {
            int k0 = ks * 16 + t * 2;
            float2 v00 = *(const float2*)(yp0 + k0);
            float2 v01 = *(const float2*)(yp0 + k0 + 8);
            float2 v10 = *(const float2*)(yp1 + k0);
            float2 v11 = *(const float2*)(yp1 + k0 + 8);
            float2 w0 = *(const float2*)(s_lnw + k0);
            float2 w1 = *(const float2*)(s_lnw + k0 + 8);
            float2 z0 = *(const float2*)(s_lnb + k0);
            float2 z1 = *(const float2*)(s_lnb + k0 + 8);
            float x00 = fmaxf((v00.x - meanA) * scaleA * w0.x + z0.x, 0.f);
            float x01 = fmaxf((v00.y - meanA) * scaleA * w0.y + z0.y, 0.f);
            float x02 = fmaxf((v01.x - meanA) * scaleA * w1.x + z1.x, 0.f);
            float x03 = fmaxf((v01.y - meanA) * scaleA * w1.y + z1.y, 0.f);
            float x10 = fmaxf((v10.x - meanB) * scaleB * w0.x + z0.x, 0.f);
            float x11 = fmaxf((v10.y - meanB) * scaleB * w0.y + z0.y, 0.f);
            float x12 = fmaxf((v11.x - meanB) * scaleB * w1.x + z1.x, 0.f);
            float x13 = fmaxf((v11.y - meanB) * scaleB * w1.y + z1.y, 0.f);
            uint32_t ah[4], al[4];
            hsplit2(x00, x01, ah[0], al[0]);
            hsplit2(x10, x11, ah[1], al[1]);
            hsplit2(x02, x03, ah[2], al[2]);
            hsplit2(x12, x13, ah[3], al[3]);
            const uint2* wh = sWh + ks * 256 + lane;
            const uint2* wl = sWl + ks * 256 + lane;
            #pragma unroll
            for (int nb = 0; nb < 8; ++nb) {
                uint2 bh = wh[nb * 32];
                uint2 bl = wl[nb * 32];
                mma_f32acc(accF[nb], ah, bh.x, bh.y);
                mma_f16acc(accH[nb], ah, bl.x, bl.y);
                mma_f16acc(accH[nb], al, bh.x, bh.y);
            }
        }
        #pragma unroll
        for (int nb = 0; nb < 8; ++nb) {
            int col = half * 64 + nb * 8 + t * 2;
            float2 bb = *(const float2*)(s_b2 + nb * 8 + t * 2);
            float2 c0 = h2_to_f2(accH[nb][0]);
            float2 c1 = h2_to_f2(accH[nb][1]);
            if (rg0 < n) {
                float2 hv = *(const float2*)(hres + (size_t)rg0 * 128 + col);
                *(float2*)(out + (size_t)rg0 * 128 + col) =
                    make_float2(accF[nb][0] + c0.x * LO_INV + bb.x + hv.x,
                                accF[nb][1] + c0.y * LO_INV + bb.y + hv.y);
            }
            if (rg1 < n) {
                float2 hv = *(const float2*)(hres + (size_t)rg1 * 128 + col);
                *(float2*)(out + (size_t)rg1 * 128 + col) =
                    make_float2(accF[nb][2] + c1.x * LO_INV + bb.x + hv.x,
                                accF[nb][3] + c1.y * LO_INV + bb.y + hv.y);
            }
        }
    }
}

// ---------------- launch ----------------
extern "C" void kernel_launch(void* const* d_in, const int* in_sizes, int n_in,
                              void* d_out, int out_size)
{
    const float* h   = (const float*)d_in[0];
    const int*   ei  = (const int*)  d_in[1];
    const float* ea  = (const float*)d_in[2];
    const float* bw  = (const float*)d_in[3];
    const float* bb  = (const float*)d_in[4];
    const float* bm  = (const float*)d_in[5];
    const float* bv  = (const float*)d_in[6];
    const float* tp  = (const float*)d_in[7];
    const float* W1  = (const float*)d_in[8];
    const float* b1  = (const float*)d_in[9];
    const float* lnw = (const float*)d_in[10];
    const float* lnb = (const float*)d_in[11];
    const float* W2  = (const float*)d_in[12];
    const float* b2  = (const float*)d_in[13];

    int n = in_sizes[0] / HF;
    int e = in_sizes[2] / HF;
    const int* src = ei;
    const int* dst = ei + e;
    int nstrips = (n + 15) / 16;

    cudaFuncSetAttribute(k_mma1, cudaFuncAttributeMaxDynamicSharedMemorySize, SMEM_MMA1);
    cudaFuncSetAttribute(k_mma2, cudaFuncAttributeMaxDynamicSharedMemorySize, SMEM_MMA2);

    k_hn_hist<<<(n * HV + 255) / 256, 256>>>((const float4*)h, (const float4*)bw,
                                             (const float4*)bb, (const float4*)bm,
                                             (const float4*)bv, dst, n, e);
    k_scan<<<1, 1024>>>(n);
    k_scatter<<<(e + 255) / 256, 256>>>(src, dst, e);
    k_agg<<<(n + 7) / 8, 256>>>((const float4*)ea, tp, n);      // <- ncu capture lands here
    k_prepw<<<64, 256>>>(W1, W2);
    k_mma1<<<304, 256, SMEM_MMA1>>>(b1, n, nstrips);
    k_mma2<<<304, 256, SMEM_MMA2>>>(b2, lnw, lnb, h, (float*)d_out, n, nstrips);
}

// round 11
// speedup vs baseline: 1.0902x; 1.0902x over previous
#include <cuda_runtime.h>
#include <cuda_fp16.h>
#include <cstdint>

#define HF 128
#define HV 32           // float4 per feature row
#define NMAX 50048
#define EMAX 800032

// ---------------- scratch (static device memory; no allocation) ----------------
__device__ float g_hn[NMAX * HF];        // relu(BN(x))
__device__ float g_u [NMAX * HF];        // agg + hn  (MLP input)
__device__ float g_y1[NMAX * 2 * HF];    // GEMM1 output (pre-LN), L2-resident
__device__ int   g_cnt[NMAX];
__device__ int   g_rs [NMAX + 1];
__device__ int   g_cur[NMAX];
__device__ int2  g_edges[EMAX];
// fragment-ordered fp16 weight images, 64KB each
__device__ uint2 g_w1h[8192];
__device__ uint2 g_w2h[8192];

// ---------------- helpers ----------------
__device__ __forceinline__ uint32_t pack2h(float a, float b) {
    __half2 h = __floats2half2_rn(a, b);
    return *reinterpret_cast<uint32_t*>(&h);
}

// f16 inputs, f32 accum
__device__ __forceinline__ void mma_f32acc(float* d, const uint32_t* a, uint32_t b0, uint32_t b1) {
    asm volatile(
        "mma.sync.aligned.m16n8k16.row.col.f32.f16.f16.f32 "
        "{%0,%1,%2,%3}, {%4,%5,%6,%7}, {%8,%9}, {%0,%1,%2,%3};"
        : "+f"(d[0]), "+f"(d[1]), "+f"(d[2]), "+f"(d[3])
        : "r"(a[0]), "r"(a[1]), "r"(a[2]), "r"(a[3]), "r"(b0), "r"(b1));
}

// ---------------- K0: hn = relu(BN(h))  +  degree histogram ----------------
__global__ void k_hn_hist(const float4* __restrict__ h,
                          const float4* __restrict__ bw, const float4* __restrict__ bb,
                          const float4* __restrict__ bm, const float4* __restrict__ bv,
                          const int* __restrict__ dst, int n, int e)
{
    int i = blockIdx.x * blockDim.x + threadIdx.x;
    if (i < e) atomicAdd(&g_cnt[dst[i]], 1);
    if (i >= n * HV) return;
    int j = i & (HV - 1);
    float4 x = h[i];
    float4 w = bw[j], b = bb[j], m = bm[j], v = bv[j];
    float4 o;
    o.x = fmaxf((x.x - m.x) * rsqrtf(v.x + 1e-5f) * w.x + b.x, 0.f);
    o.y = fmaxf((x.y - m.y) * rsqrtf(v.y + 1e-5f) * w.y + b.y, 0.f);
    o.z = fmaxf((x.z - m.z) * rsqrtf(v.z + 1e-5f) * w.z + b.z, 0.f);
    o.w = fmaxf((x.w - m.w) * rsqrtf(v.w + 1e-5f) * w.w + b.w, 0.f);
    ((float4*)g_hn)[i] = o;
}

// ---------------- K1: coalesced exclusive scan (single block) ----------------
__global__ void k_scan(int n)
{
    __shared__ int wsum[32];
    __shared__ int s_carry;
    int tid = threadIdx.x, lane = tid & 31, wid = tid >> 5;
    if (tid == 0) s_carry = 0;
    __syncthreads();
    int nIter = (n + 1023) >> 10;
    for (int it = 0; it < nIter; ++it) {
        int idx = (it << 10) + tid;
        int v = (idx < n) ? g_cnt[idx] : 0;
        int x = v;
        #pragma unroll
        for (int o = 1; o < 32; o <<= 1) {
            int u = __shfl_up_sync(0xffffffffu, x, o);
            if (lane >= o) x += u;
        }
        if (lane == 31) wsum[wid] = x;
        __syncthreads();
        if (wid == 0) {
            int w = wsum[lane];
            #pragma unroll
            for (int o = 1; o < 32; o <<= 1) {
                int u = __shfl_up_sync(0xffffffffu, w, o);
                if (lane >= o) w += u;
            }
            wsum[lane] = w;
        }
        __syncthreads();
        int carry = s_carry;
        int excl = x - v + (wid > 0 ? wsum[wid - 1] : 0) + carry;
        if (idx < n) { g_rs[idx] = excl; g_cur[idx] = excl; g_cnt[idx] = 0; }
        __syncthreads();
        if (tid == 0) s_carry = carry + wsum[31];
        __syncthreads();
    }
    if (tid == 0) g_rs[n] = s_carry;
}

// ---------------- K2: scatter edges by dst ----------------
__global__ void k_scatter(const int* __restrict__ src, const int* __restrict__ dst, int e)
{
    int i = blockIdx.x * blockDim.x + threadIdx.x;
    if (i >= e) return;
    int d = dst[i];
    int s = src[i];
    int p = atomicAdd(&g_cur[d], 1);
    g_edges[p] = make_int2(s, i);
}

// ---------------- K3: one-pass softmax aggregation (warp per dst node) ----------------
#define EDGE_ACC(a, hv)                                               \
    {                                                                 \
        float m0 = fmaxf(a.x + hv.x, 0.f) + 1e-7f;                    \
        float m1 = fmaxf(a.y + hv.y, 0.f) + 1e-7f;                    \
        float m2 = fmaxf(a.z + hv.z, 0.f) + 1e-7f;                    \
        float m3 = fmaxf(a.w + hv.w, 0.f) + 1e-7f;                    \
        float e0 = __expf(m0 * t);                                    \
        float e1 = __expf(m1 * t);                                    \
        float e2 = __expf(m2 * t);                                    \
        float e3 = __expf(m3 * t);                                    \
        S.x += e0; P.x = fmaf(m0, e0, P.x);                           \
        S.y += e1; P.y = fmaf(m1, e1, P.y);                           \
        S.z += e2; P.z = fmaf(m2, e2, P.z);                           \
        S.w += e3; P.w = fmaf(m3, e3, P.w);                           \
    }

__global__ void __launch_bounds__(256) k_agg(const float4* __restrict__ ea,
                                             const float* __restrict__ tp, int n)
{
    int warp = (blockIdx.x * blockDim.x + threadIdx.x) >> 5;
    int lane = threadIdx.x & 31;
    if (warp >= n) return;
    float t = __ldg(tp);
    int s0 = g_rs[warp], s1 = g_rs[warp + 1];
    const float4* hn4 = (const float4*)g_hn;
    float4 S = make_float4(0.f, 0.f, 0.f, 0.f);
    float4 P = make_float4(0.f, 0.f, 0.f, 0.f);

    int i = s0;
    for (; i + 4 <= s1; i += 4) {
        int2 q0 = g_edges[i + 0];
        int2 q1 = g_edges[i + 1];
        int2 q2 = g_edges[i + 2];
        int2 q3 = g_edges[i + 3];
        float4 a0 = ea [(size_t)q0.y * HV + lane];
        float4 h0 = hn4[(size_t)q0.x * HV + lane];
        float4 a1 = ea [(size_t)q1.y * HV + lane];
        float4 h1 = hn4[(size_t)q1.x * HV + lane];
        float4 a2 = ea [(size_t)q2.y * HV + lane];
        float4 h2 = hn4[(size_t)q2.x * HV + lane];
        float4 a3 = ea [(size_t)q3.y * HV + lane];
        float4 h3 = hn4[(size_t)q3.x * HV + lane];
        EDGE_ACC(a0, h0);
        EDGE_ACC(a1, h1);
        EDGE_ACC(a2, h2);
        EDGE_ACC(a3, h3);
    }
    for (; i < s1; ++i) {
        int2 q = g_edges[i];
        float4 a  = ea [(size_t)q.y * HV + lane];
        float4 hv = hn4[(size_t)q.x * HV + lane];
        EDGE_ACC(a, hv);
    }

    float4 hd = hn4[warp * HV + lane];
    float4 u;
    u.x = P.x / (S.x + 1e-16f) + hd.x;
    u.y = P.y / (S.y + 1e-16f) + hd.y;
    u.z = P.z / (S.z + 1e-16f) + hd.z;
    u.w = P.w / (S.w + 1e-16f) + hd.w;
    ((float4*)g_u)[warp * HV + lane] = u;
}

// ---------------- K4: prep fragment-ordered fp16 weight images ----------------
// W1: idx = ks(8)*1024 + nb(32)*32 + lane.  W2: idx = ks(16)*512 + nb(16)*32 + lane.
// B frag (16x8 col-major): b0 = rows {k0, k0+1}, b1 = rows {k0+8, k0+9}, col n.
__global__ void k_prepw(const float* __restrict__ W1, const float* __restrict__ W2)
{
    int idx = blockIdx.x * blockDim.x + threadIdx.x;
    if (idx >= 16384) return;
    const float* W;
    uint2* ih;
    int ks, nb, l, ldn;
    if (idx < 8192) {
        int j = idx;
        ks = j >> 10; nb = (j >> 5) & 31; l = j & 31;
        W = W1; ih = g_w1h; ldn = 256;
    } else {
        int j = idx - 8192;
        ks = j >> 9; nb = (j >> 5) & 15; l = j & 31;
        W = W2; ih = g_w2h; ldn = 128;
    }
    int k0 = ks * 16 + (l & 3) * 2;
    int nn = nb * 8 + (l >> 2);
    float x00 = W[(size_t)(k0 + 0) * ldn + nn];
    float x01 = W[(size_t)(k0 + 1) * ldn + nn];
    float x10 = W[(size_t)(k0 + 8) * ldn + nn];
    float x11 = W[(size_t)(k0 + 9) * ldn + nn];
    ih[idx & 8191] = make_uint2(pack2h(x00, x01), pack2h(x10, x11));
}

// ---------------- K5: GEMM1 via mma.sync  y1 = u @ W1 + b1 ----------------
// 304 CTAs = 2/SM; CTA owns a 128-col half (32KB weights); single fp16 term.
#define SMEM_MMA1 (32768 + 512)
__global__ void __launch_bounds__(256, 2) k_mma1(const float* __restrict__ b1,
                                                 int n, int nstrips)
{
    extern __shared__ char smem[];
    uint2* sWh  = (uint2*)smem;             // 4096 (32KB): 8 ks x 16 nb x 32 lanes
    float* s_b1 = (float*)(smem + 32768);   // 128
    int tid = threadIdx.x, wid = tid >> 5, lane = tid & 31;
    int half = blockIdx.x & 1, slot = blockIdx.x >> 1;

    for (int i = tid; i < 4096; i += 256) {
        int ks = i >> 9, rem = i & 511;                 // ks in [0,8), rem = nb*32+lane
        sWh[i] = g_w1h[ks * 1024 + half * 512 + rem];
    }
    if (tid < 128) s_b1[tid] = b1[half * 128 + tid];
    __syncthreads();

    int g = lane >> 2, t = lane & 3;
    int nwarps = 152 * 8;
    for (int strip = slot * 8 + wid; strip < nstrips; strip += nwarps) {
        int rg0 = strip * 16 + g;
        int rg1 = rg0 + 8;
        const float* up0 = g_u + (size_t)rg0 * 128;
        const float* up1 = g_u + (size_t)rg1 * 128;
        float acc[16][4];
        #pragma unroll
        for (int nb = 0; nb < 16; ++nb) {
            acc[nb][0] = 0.f; acc[nb][1] = 0.f; acc[nb][2] = 0.f; acc[nb][3] = 0.f;
        }
        #pragma unroll
        for (int ks = 0; ks < 8; ++ks) {
            int k0 = ks * 16 + t * 2;
            float2 v00 = *(const float2*)(up0 + k0);
            float2 v01 = *(const float2*)(up0 + k0 + 8);
            float2 v10 = *(const float2*)(up1 + k0);
            float2 v11 = *(const float2*)(up1 + k0 + 8);
            uint32_t ah[4];
            ah[0] = pack2h(v00.x, v00.y);
            ah[1] = pack2h(v10.x, v10.y);
            ah[2] = pack2h(v01.x, v01.y);
            ah[3] = pack2h(v11.x, v11.y);
            const uint2* wh = sWh + ks * 512 + lane;
            #pragma unroll
            for (int nb = 0; nb < 16; ++nb) {
                uint2 bh = wh[nb * 32];
                mma_f32acc(acc[nb], ah, bh.x, bh.y);
            }
        }
        #pragma unroll
        for (int nb = 0; nb < 16; ++nb) {
            int col = half * 128 + nb * 8 + t * 2;
            float2 bb = *(const float2*)(s_b1 + nb * 8 + t * 2);
            if (rg0 < n)
                *(float2*)(g_y1 + (size_t)rg0 * 256 + col) =
                    make_float2(acc[nb][0] + bb.x, acc[nb][1] + bb.y);
            if (rg1 < n)
                *(float2*)(g_y1 + (size_t)rg1 * 256 + col) =
                    make_float2(acc[nb][2] + bb.x, acc[nb][3] + bb.y);
        }
    }
}

// ---------------- K6: GEMM2 via mma.sync  out = relu(LN(y1)) @ W2 + b2 + h ----------------
// 304 CTAs = 2/SM; CTA owns a 64-col half (32KB weights); single fp16 term.
#define SMEM_MMA2 (32768 + 2304)
__global__ void __launch_bounds__(256, 2) k_mma2(const float* __restrict__ b2,
                                                 const float* __restrict__ lnw,
                                                 const float* __restrict__ lnb,
                                                 const float* __restrict__ hres,
                                                 float* __restrict__ out,
                                                 int n, int nstrips)
{
    extern __shared__ char smem[];
    uint2* sWh   = (uint2*)smem;                     // 4096 (32KB): 16 ks x 8 nb x 32 lanes
    float* s_lnw = (float*)(smem + 32768);           // 256
    float* s_lnb = (float*)(smem + 32768 + 1024);    // 256
    float* s_b2  = (float*)(smem + 32768 + 2048);    // 64
    int tid = threadIdx.x, wid = tid >> 5, lane = tid & 31;
    int half = blockIdx.x & 1, slot = blockIdx.x >> 1;

    for (int i = tid; i < 4096; i += 256) {
        int ks = i >> 8, rem = i & 255;                 // ks in [0,16), rem = nb*32+lane
        sWh[i] = g_w2h[ks * 512 + half * 256 + rem];
    }
    if (tid < 256) { s_lnw[tid] = lnw[tid]; s_lnb[tid] = lnb[tid]; }
    if (tid < 64) s_b2[tid] = b2[half * 64 + tid];
    __syncthreads();

    int g = lane >> 2, t = lane & 3;
    int nwarps = 152 * 8;
    for (int strip = slot * 8 + wid; strip < nstrips; strip += nwarps) {
        // ---- LN stats for the 16 rows of this strip ----
        float meanA = 0.f, scaleA = 0.f, meanB = 0.f, scaleB = 0.f;
        #pragma unroll
        for (int r = 0; r < 16; ++r) {
            int grow = strip * 16 + r;
            const float4* yp = (const float4*)(g_y1 + (size_t)grow * 256);
            float4 a = yp[lane * 2], b = yp[lane * 2 + 1];
            float s  = a.x + a.y + a.z + a.w + b.x + b.y + b.z + b.w;
            float s2 = a.x*a.x + a.y*a.y + a.z*a.z + a.w*a.w
                     + b.x*b.x + b.y*b.y + b.z*b.z + b.w*b.w;
            #pragma unroll
            for (int o = 16; o > 0; o >>= 1) {
                s  += __shfl_xor_sync(0xffffffffu, s, o);
                s2 += __shfl_xor_sync(0xffffffffu, s2, o);
            }
            float mean = s * (1.f / 256.f);
            float var = fmaxf(s2 * (1.f / 256.f) - mean * mean, 0.f);
            float sc = rsqrtf(var + 1e-5f);
            if (r == g)     { meanA = mean; scaleA = sc; }
            if (r == g + 8) { meanB = mean; scaleB = sc; }
        }

        int rg0 = strip * 16 + g, rg1 = rg0 + 8;
        const float* yp0 = g_y1 + (size_t)rg0 * 256;
        const float* yp1 = g_y1 + (size_t)rg1 * 256;
        float acc[8][4];
        #pragma unroll
        for (int nb = 0; nb < 8; ++nb) {
            acc[nb][0] = 0.f; acc[nb][1] = 0.f; acc[nb][2] = 0.f; acc[nb][3] = 0.f;
        }
        #pragma unroll
        for (int ks = 0; ks < 16; ++ks) {
            int k0 = ks * 16 + t * 2;
            float2 v00 = *(const float2*)(yp0 + k0);
            float2 v01 = *(const float2*)(yp0 + k0 + 8);
            float2 v10 = *(const float2*)(yp1 + k0);
            float2 v11 = *(const float2*)(yp1 + k0 + 8);
            float2 w0 = *(const float2*)(s_lnw + k0);
            float2 w1 = *(const float2*)(s_lnw + k0 + 8);
            float2 z0 = *(const float2*)(s_lnb + k0);
            float2 z1 = *(const float2*)(s_lnb + k0 + 8);
            float x00 = fmaxf((v00.x - meanA) * scaleA * w0.x + z0.x, 0.f);
            float x01 = fmaxf((v00.y - meanA) * scaleA * w0.y + z0.y, 0.f);
            float x02 = fmaxf((v01.x - meanA) * scaleA * w1.x + z1.x, 0.f);
            float x03 = fmaxf((v01.y - meanA) * scaleA * w1.y + z1.y, 0.f);
            float x10 = fmaxf((v10.x - meanB) * scaleB * w0.x + z0.x, 0.f);
            float x11 = fmaxf((v10.y - meanB) * scaleB * w0.y + z0.y, 0.f);
            float x12 = fmaxf((v11.x - meanB) * scaleB * w1.x + z1.x, 0.f);
            float x13 = fmaxf((v11.y - meanB) * scaleB * w1.y + z1.y, 0.f);
            uint32_t ah[4];
            ah[0] = pack2h(x00, x01);
            ah[1] = pack2h(x10, x11);
            ah[2] = pack2h(x02, x03);
            ah[3] = pack2h(x12, x13);
            const uint2* wh = sWh + ks * 256 + lane;
            #pragma unroll
            for (int nb = 0; nb < 8; ++nb) {
                uint2 bh = wh[nb * 32];
                mma_f32acc(acc[nb], ah, bh.x, bh.y);
            }
        }
        #pragma unroll
        for (int nb = 0; nb < 8; ++nb) {
            int col = half * 64 + nb * 8 + t * 2;
            float2 bb = *(const float2*)(s_b2 + nb * 8 + t * 2);
            if (rg0 < n) {
                float2 hv = *(const float2*)(hres + (size_t)rg0 * 128 + col);
                *(float2*)(out + (size_t)rg0 * 128 + col) =
                    make_float2(acc[nb][0] + bb.x + hv.x, acc[nb][1] + bb.y + hv.y);
            }
            if (rg1 < n) {
                float2 hv = *(const float2*)(hres + (size_t)rg1 * 128 + col);
                *(float2*)(out + (size_t)rg1 * 128 + col) =
                    make_float2(acc[nb][2] + bb.x + hv.x, acc[nb][3] + bb.y + hv.y);
            }
        }
    }
}

// ---------------- launch ----------------
extern "C" void kernel_launch(void* const* d_in, const int* in_sizes, int n_in,
                              void* d_out, int out_size)
{
    const float* h   = (const float*)d_in[0];
    const int*   ei  = (const int*)  d_in[1];
    const float* ea  = (const float*)d_in[2];
    const float* bw  = (const float*)d_in[3];
    const float* bb  = (const float*)d_in[4];
    const float* bm  = (const float*)d_in[5];
    const float* bv  = (const float*)d_in[6];
    const float* tp  = (const float*)d_in[7];
    const float* W1  = (const float*)d_in[8];
    const float* b1  = (const float*)d_in[9];
    const float* lnw = (const float*)d_in[10];
    const float* lnb = (const float*)d_in[11];
    const float* W2  = (const float*)d_in[12];
    const float* b2  = (const float*)d_in[13];

    int n = in_sizes[0] / HF;
    int e = in_sizes[2] / HF;
    const int* src = ei;
    const int* dst = ei + e;
    int nstrips = (n + 15) / 16;

    cudaFuncSetAttribute(k_mma1, cudaFuncAttributeMaxDynamicSharedMemorySize, SMEM_MMA1);
    cudaFuncSetAttribute(k_mma2, cudaFuncAttributeMaxDynamicSharedMemorySize, SMEM_MMA2);

    k_hn_hist<<<(n * HV + 255) / 256, 256>>>((const float4*)h, (const float4*)bw,
                                             (const float4*)bb, (const float4*)bm,
                                             (const float4*)bv, dst, n, e);
    k_scan<<<1, 1024>>>(n);
    k_scatter<<<(e + 255) / 256, 256>>>(src, dst, e);
    k_agg<<<(n + 7) / 8, 256>>>((const float4*)ea, tp, n);      // <- ncu capture lands here
    k_prepw<<<64, 256>>>(W1, W2);
    k_mma1<<<304, 256, SMEM_MMA1>>>(b1, n, nstrips);
    k_mma2<<<304, 256, SMEM_MMA2>>>(b2, lnw, lnb, h, (float*)d_out, n, nstrips);
}